// round 9
// baseline (speedup 1.0000x reference)
#include <cuda_runtime.h>
#include <math.h>

#define B 32
#define N 512
#define FIN 16
#define H 8
#define DH 8
#define DOUT 32

typedef unsigned long long ull;

// ---------------- scratch ----------------
__device__ float g_Wh[B*N*H*DH];          // [b][n][h*8+d]
__device__ float g_f1[B*N*H];             // [b][n][h]
__device__ float g_f2[B*N*H];             // [b][n][h]
__device__ float g_hcat[B*N*H*DH];        // [b][n][h*8+d]
__device__ float g_Who[B*N*DOUT];         // [b][n][d]
__device__ float g_g1[B*N];
__device__ float g_g2[B*N];
__device__ float g_out[B*N*DOUT];         // [b][k]
__device__ float g_qpart[64*B*N];         // split-K partials
__device__ int   g_cnt[B*N];
__device__ int   g_nbr[B*N*N];

// ---------------- helpers ----------------
__device__ __forceinline__ float lrelu(float x){ return x >= 0.f ? x : 0.2f * x; }
__device__ __forceinline__ float elu(float x){ return x > 0.f ? x : expm1f(x); }

__device__ __forceinline__ ull fma2(ull a, ull b, ull c){
    ull d;
    asm("fma.rn.f32x2 %0, %1, %2, %3;" : "=l"(d) : "l"(a), "l"(b), "l"(c));
    return d;
}
__device__ __forceinline__ ull pack2(float x){
    ull r;
    asm("mov.b64 %0, {%1, %1};" : "=l"(r) : "f"(x));
    return r;
}
__device__ __forceinline__ void unpack2(ull v, float& lo, float& hi){
    asm("mov.b64 {%0, %1}, %2;" : "=f"(lo), "=f"(hi) : "l"(v));
}

// ---------------- K0: compact adjacency rows into neighbor lists ----------------
__global__ void k0_compact(const float* __restrict__ adj){
    int t = threadIdx.x, w = t >> 5, lane = t & 31;
    int row = blockIdx.x * 8 + w;
    const float* arow = adj + (size_t)row * N;
    float av[16];
#pragma unroll
    for (int c = 0; c < 16; c++) av[c] = arow[c*32 + lane];
    unsigned bal[16];
#pragma unroll
    for (int c = 0; c < 16; c++) bal[c] = __ballot_sync(0xffffffffu, av[c] > 0.f);
    int* dst = g_nbr + (size_t)row * N;
    int base = 0;
    unsigned lmask = (1u << lane) - 1u;
#pragma unroll
    for (int c = 0; c < 16; c++){
        unsigned b = bal[c];
        if ((b >> lane) & 1u) dst[base + __popc(b & lmask)] = c*32 + lane;
        base += __popc(b);
    }
    if (lane == 0) g_cnt[row] = base;
}

// ---------------- K1: Wh = xv @ W_heads ; f1 ; f2 ----------------
__global__ void k1_proj(const float* __restrict__ xv,
                        const float* __restrict__ Wheads,
                        const float* __restrict__ a1,
                        const float* __restrict__ a2){
    __shared__ float Ws[H*FIN*DH];
    __shared__ float a1s[H*DH], a2s[H*DH];
    int t = threadIdx.x;
    for (int i = t; i < H*FIN*DH; i += 256) Ws[i] = Wheads[i];
    if (t < H*DH){ a1s[t] = a1[t]; a2s[t] = a2[t]; }
    __syncthreads();

    int gt = blockIdx.x * 256 + t;
    int h  = gt & 7;
    int bn = gt >> 3;
    const float* xr = xv + bn * FIN;

    float wh[DH];
#pragma unroll
    for (int d = 0; d < DH; d++) wh[d] = 0.f;
#pragma unroll
    for (int f = 0; f < FIN; f++){
        float x = xr[f];
        const float* wf = Ws + (h*FIN + f)*DH;
#pragma unroll
        for (int d = 0; d < DH; d++) wh[d] += x * wf[d];
    }
    float f1v = 0.f, f2v = 0.f;
#pragma unroll
    for (int d = 0; d < DH; d++){
        f1v += wh[d] * a1s[h*DH + d];
        f2v += wh[d] * a2s[h*DH + d];
    }
    float* dstp = g_Wh + (size_t)bn*64 + h*8;
    ((float4*)dstp)[0] = make_float4(wh[0], wh[1], wh[2], wh[3]);
    ((float4*)dstp)[1] = make_float4(wh[4], wh[5], wh[6], wh[7]);
    g_f1[bn*8 + h] = f1v;
    g_f2[bn*8 + h] = f2v;
}

// ---------------- K2: layer-1 attention, thread=(h,d), no max pass, chunk-4 ----------------
__global__ void k2_gat(){
    int t = threadIdx.x;
    int g = t >> 6, u = t & 63;         // 4 rows/block, 64 threads/row
    int h = u >> 3;
    int row = blockIdx.x * 4 + g;
    int b = row >> 9;

    int cnt = g_cnt[row];
    const int* __restrict__ jl = g_nbr + (size_t)row * N;
    const float* __restrict__ f2B = g_f2 + (size_t)b * N * 8;
    const float* __restrict__ WhB = g_Wh + (size_t)b * N * 64;
    float f1i = g_f1[row*8 + h];

    float s = 0.f, acc = 0.f;
    if (cnt > 0){
        int k = 0;
        for (; k + 4 <= cnt; k += 4){
            int4 j4 = *(const int4*)(jl + k);
            float e0 = f2B[j4.x*8 + h];
            float e1 = f2B[j4.y*8 + h];
            float e2 = f2B[j4.z*8 + h];
            float e3 = f2B[j4.w*8 + h];
            float w0 = WhB[(size_t)j4.x*64 + u];
            float w1 = WhB[(size_t)j4.y*64 + u];
            float w2 = WhB[(size_t)j4.z*64 + u];
            float w3 = WhB[(size_t)j4.w*64 + u];
            float p0 = expf(lrelu(f1i + e0));
            float p1 = expf(lrelu(f1i + e1));
            float p2 = expf(lrelu(f1i + e2));
            float p3 = expf(lrelu(f1i + e3));
            s += p0; s += p1; s += p2; s += p3;
            acc += p0*w0; acc += p1*w1; acc += p2*w2; acc += p3*w3;
        }
        for (; k < cnt; k++){
            int j = jl[k];
            float p = expf(lrelu(f1i + f2B[j*8 + h]));
            s += p;
            acc += p * WhB[(size_t)j*64 + u];
        }
    } else {
        s = (float)N;
        for (int j = 0; j < N; j++) acc += WhB[(size_t)j*64 + u];
    }
    g_hcat[(size_t)row*64 + u] = elu(acc / s);
}

// ---------------- K3: Who = h_cat @ W_out (16 rows/block, 2 rows/warp) ----------------
__global__ void k3_who(const float* __restrict__ Wout,
                       const float* __restrict__ a1o,
                       const float* __restrict__ a2o){
    __shared__ float Ws[64*32];     // 8 KB
    __shared__ float a1s[32], a2s[32];
    int t = threadIdx.x;
    for (int i = t; i < 64*32; i += 256) Ws[i] = Wout[i];
    if (t < 32){ a1s[t] = a1o[t]; a2s[t] = a2o[t]; }
    __syncthreads();

    int w = t >> 5, lane = t & 31;
    int row0 = blockIdx.x*16 + w*2;
    const float4* h0 = (const float4*)(g_hcat + (size_t)row0*64);
    const float4* h1 = h0 + 16;

    float who0 = 0.f, who1 = 0.f;
#pragma unroll
    for (int f4 = 0; f4 < 16; f4++){
        float4 a = h0[f4];          // warp-broadcast LDG.128
        float4 c = h1[f4];
        float w0 = Ws[(4*f4+0)*32 + lane];
        float w1 = Ws[(4*f4+1)*32 + lane];
        float w2 = Ws[(4*f4+2)*32 + lane];
        float w3 = Ws[(4*f4+3)*32 + lane];
        who0 += a.x*w0 + a.y*w1 + a.z*w2 + a.w*w3;
        who1 += c.x*w0 + c.y*w1 + c.z*w2 + c.w*w3;
    }
    g_Who[(size_t)row0*32 + lane]     = who0;
    g_Who[(size_t)(row0+1)*32 + lane] = who1;

    float v10 = who0*a1s[lane], v20 = who0*a2s[lane];
    float v11 = who1*a1s[lane], v21 = who1*a2s[lane];
#pragma unroll
    for (int o = 16; o; o >>= 1){
        v10 += __shfl_xor_sync(0xffffffffu, v10, o);
        v20 += __shfl_xor_sync(0xffffffffu, v20, o);
        v11 += __shfl_xor_sync(0xffffffffu, v11, o);
        v21 += __shfl_xor_sync(0xffffffffu, v21, o);
    }
    if (lane == 0){
        g_g1[row0] = v10;   g_g2[row0] = v20;
        g_g1[row0+1] = v11; g_g2[row0+1] = v21;
    }
}

// ---------------- K4: layer-2 attention, lane=dim, no max pass, chunk-4 ----------------
__global__ void k4_outattn(){
    int t = threadIdx.x, w = t >> 5, lane = t & 31;
    int row = blockIdx.x * 8 + w;
    int b = row >> 9;
    int cnt = g_cnt[row];
    const int* __restrict__ jl = g_nbr + (size_t)row * N;

    float g1i = g_g1[row];
    const float* __restrict__ g2b  = g_g2 + b * N;
    const float* __restrict__ WhoB = g_Who + (size_t)b * N * DOUT;

    float s = 0.f, tot = 0.f;
    if (cnt > 0){
        int k = 0;
        for (; k + 4 <= cnt; k += 4){
            int4 j4 = *(const int4*)(jl + k);
            float e0 = g2b[j4.x];
            float e1 = g2b[j4.y];
            float e2 = g2b[j4.z];
            float e3 = g2b[j4.w];
            float w0 = WhoB[(size_t)j4.x*DOUT + lane];
            float w1 = WhoB[(size_t)j4.y*DOUT + lane];
            float w2 = WhoB[(size_t)j4.z*DOUT + lane];
            float w3 = WhoB[(size_t)j4.w*DOUT + lane];
            float p0 = expf(lrelu(g1i + e0));
            float p1 = expf(lrelu(g1i + e1));
            float p2 = expf(lrelu(g1i + e2));
            float p3 = expf(lrelu(g1i + e3));
            s += p0; s += p1; s += p2; s += p3;
            tot += p0*w0; tot += p1*w1; tot += p2*w2; tot += p3*w3;
        }
        for (; k < cnt; k++){
            int j = jl[k];
            float p = expf(lrelu(g1i + g2b[j]));
            s += p;
            tot += p * WhoB[(size_t)j*DOUT + lane];
        }
    } else {
        s = (float)N;
        for (int j = 0; j < N; j++) tot += WhoB[(size_t)j*DOUT + lane];
    }
    g_out[(size_t)row*DOUT + lane] = elu(tot / s);
}

// ---------------- K5: q_part = out[B,16384] @ W_q[16384,512] (split-K 16-way, f32x2) ----------------
__global__ void k5_qgemm(const float* __restrict__ Wq){
    __shared__ float sm[256*36];
    int t = threadIdx.x;
    int c = blockIdx.x * 64 + (t & 63);
    int g = t >> 6;
    ull acc2[16];
#pragma unroll
    for (int q = 0; q < 16; q++) acc2[q] = 0ull;

    int kb0 = blockIdx.y * 1024;
    for (int st = 0; st < 4; st++){
        int kbase = kb0 + st*256;
        __syncthreads();
        for (int idx = t; idx < 2048; idx += 256){
            int b  = idx >> 6;
            int kq = idx & 63;
            float4 v = *(const float4*)(g_out + (size_t)b*16384 + kbase + kq*4);
            float* dst = sm + kq*4*36 + b;
            dst[0]   = v.x; dst[36]  = v.y; dst[72]  = v.z; dst[108] = v.w;
        }
        __syncthreads();

        const float* wq  = Wq + (size_t)(kbase + g*64)*512 + c;
        const float* smg = sm + (g*64)*36;
#pragma unroll 4
        for (int kk = 0; kk < 64; kk++){
            ull wv2 = pack2(wq[(size_t)kk*512]);
            const ull* o2 = (const ull*)(smg + kk*36);
#pragma unroll
            for (int q = 0; q < 16; q++)
                acc2[q] = fma2(o2[q], wv2, acc2[q]);
        }
    }
    float* qp = g_qpart + (size_t)(blockIdx.y*4 + g) * (B*N);
#pragma unroll
    for (int q = 0; q < 16; q++){
        float lo, hi; unpack2(acc2[q], lo, hi);
        qp[(2*q)*N + c]   = lo;
        qp[(2*q+1)*N + c] = hi;
    }
}

// ---------------- K6: q = sum of 64 partials + b_q ----------------
__global__ void k6_reduce(const float* __restrict__ bq, float* __restrict__ q){
    int t = blockIdx.x * 128 + threadIdx.x;
    int c = t & 511;
    float s = bq[c];
#pragma unroll
    for (int p = 0; p < 64; p++) s += g_qpart[(size_t)p*(B*N) + t];
    q[t] = s;
}

// ---------------- launch ----------------
extern "C" void kernel_launch(void* const* d_in, const int* in_sizes, int n_in,
                              void* d_out, int out_size){
    const float* xv    = (const float*)d_in[0];
    const float* adj   = (const float*)d_in[1];
    const float* Whead = (const float*)d_in[2];
    const float* a1    = (const float*)d_in[3];
    const float* a2    = (const float*)d_in[4];
    const float* Wout  = (const float*)d_in[5];
    const float* a1o   = (const float*)d_in[6];
    const float* a2o   = (const float*)d_in[7];
    const float* Wq    = (const float*)d_in[8];
    const float* bq    = (const float*)d_in[9];
    float* q = (float*)d_out;

    k0_compact<<<B*N/8, 256>>>(adj);
    k1_proj   <<<512, 256>>>(xv, Whead, a1, a2);
    k2_gat    <<<B*N/4, 256>>>();
    k3_who    <<<B*N/16, 256>>>(Wout, a1o, a2o);
    k4_outattn<<<B*N/8, 256>>>();
    k5_qgemm  <<<dim3(8, 16), 256>>>(Wq);
    k6_reduce <<<128, 128>>>(bq, q);
}

// round 10
// speedup vs baseline: 1.2468x; 1.2468x over previous
#include <cuda_runtime.h>
#include <math.h>

#define B 32
#define N 512
#define FIN 16
#define H 8
#define DH 8
#define DOUT 32

typedef unsigned long long ull;

// ---------------- scratch ----------------
__device__ float g_Wh[B*N*H*DH];          // [b][n][h*8+d]
__device__ float g_f1[B*N*H];             // [b][n][h]
__device__ float g_f2[B*N*H];             // [b][n][h]
__device__ float g_hcat[B*N*H*DH];        // [b][n][h*8+d]
__device__ float g_Who[B*N*DOUT];         // [b][n][d]
__device__ float g_g1[B*N];
__device__ float g_g2[B*N];
__device__ float g_outT[N*DOUT*B];        // [k][b], k = n*32+d  (2 MB)
__device__ float g_qpart[128*B*N];        // split-K partials
__device__ int   g_cnt[B*N];
__device__ int   g_nbr[B*N*N];

// ---------------- helpers ----------------
__device__ __forceinline__ float lrelu(float x){ return x >= 0.f ? x : 0.2f * x; }
__device__ __forceinline__ float elu(float x){ return x > 0.f ? x : expm1f(x); }

__device__ __forceinline__ ull fma2(ull a, ull b, ull c){
    ull d;
    asm("fma.rn.f32x2 %0, %1, %2, %3;" : "=l"(d) : "l"(a), "l"(b), "l"(c));
    return d;
}
__device__ __forceinline__ ull pack2(float x){
    ull r;
    asm("mov.b64 %0, {%1, %1};" : "=l"(r) : "f"(x));
    return r;
}
__device__ __forceinline__ void unpack2(ull v, float& lo, float& hi){
    asm("mov.b64 {%0, %1}, %2;" : "=f"(lo), "=f"(hi) : "l"(v));
}

// ---------------- K0: compact adjacency rows into neighbor lists ----------------
__global__ void k0_compact(const float* __restrict__ adj){
    int t = threadIdx.x, w = t >> 5, lane = t & 31;
    int row = blockIdx.x * 8 + w;
    const float* arow = adj + (size_t)row * N;
    float av[16];
#pragma unroll
    for (int c = 0; c < 16; c++) av[c] = arow[c*32 + lane];
    unsigned bal[16];
#pragma unroll
    for (int c = 0; c < 16; c++) bal[c] = __ballot_sync(0xffffffffu, av[c] > 0.f);
    int* dst = g_nbr + (size_t)row * N;
    int base = 0;
    unsigned lmask = (1u << lane) - 1u;
#pragma unroll
    for (int c = 0; c < 16; c++){
        unsigned b = bal[c];
        if ((b >> lane) & 1u) dst[base + __popc(b & lmask)] = c*32 + lane;
        base += __popc(b);
    }
    if (lane == 0) g_cnt[row] = base;
}

// ---------------- K1: Wh = xv @ W_heads ; f1 ; f2 ----------------
__global__ void k1_proj(const float* __restrict__ xv,
                        const float* __restrict__ Wheads,
                        const float* __restrict__ a1,
                        const float* __restrict__ a2){
    __shared__ float Ws[H*FIN*DH];
    __shared__ float a1s[H*DH], a2s[H*DH];
    int t = threadIdx.x;
    for (int i = t; i < H*FIN*DH; i += 256) Ws[i] = Wheads[i];
    if (t < H*DH){ a1s[t] = a1[t]; a2s[t] = a2[t]; }
    __syncthreads();

    int gt = blockIdx.x * 256 + t;
    int h  = gt & 7;
    int bn = gt >> 3;
    const float* xr = xv + bn * FIN;

    float wh[DH];
#pragma unroll
    for (int d = 0; d < DH; d++) wh[d] = 0.f;
#pragma unroll
    for (int f = 0; f < FIN; f++){
        float x = xr[f];
        const float* wf = Ws + (h*FIN + f)*DH;
#pragma unroll
        for (int d = 0; d < DH; d++) wh[d] += x * wf[d];
    }
    float f1v = 0.f, f2v = 0.f;
#pragma unroll
    for (int d = 0; d < DH; d++){
        f1v += wh[d] * a1s[h*DH + d];
        f2v += wh[d] * a2s[h*DH + d];
    }
    float* dstp = g_Wh + (size_t)bn*64 + h*8;
    ((float4*)dstp)[0] = make_float4(wh[0], wh[1], wh[2], wh[3]);
    ((float4*)dstp)[1] = make_float4(wh[4], wh[5], wh[6], wh[7]);
    g_f1[bn*8 + h] = f1v;
    g_f2[bn*8 + h] = f2v;
}

// ---------------- K2: layer-1 attention, thread=(h,d), no max pass, chunk-4 ----------------
__global__ void k2_gat(){
    int t = threadIdx.x;
    int g = t >> 6, u = t & 63;
    int h = u >> 3;
    int row = blockIdx.x * 4 + g;
    int b = row >> 9;

    int cnt = g_cnt[row];
    const int* __restrict__ jl = g_nbr + (size_t)row * N;
    const float* __restrict__ f2B = g_f2 + (size_t)b * N * 8;
    const float* __restrict__ WhB = g_Wh + (size_t)b * N * 64;
    float f1i = g_f1[row*8 + h];

    float s = 0.f, acc = 0.f;
    if (cnt > 0){
        int k = 0;
        for (; k + 4 <= cnt; k += 4){
            int4 j4 = *(const int4*)(jl + k);
            float e0 = f2B[j4.x*8 + h];
            float e1 = f2B[j4.y*8 + h];
            float e2 = f2B[j4.z*8 + h];
            float e3 = f2B[j4.w*8 + h];
            float w0 = WhB[(size_t)j4.x*64 + u];
            float w1 = WhB[(size_t)j4.y*64 + u];
            float w2 = WhB[(size_t)j4.z*64 + u];
            float w3 = WhB[(size_t)j4.w*64 + u];
            float p0 = expf(lrelu(f1i + e0));
            float p1 = expf(lrelu(f1i + e1));
            float p2 = expf(lrelu(f1i + e2));
            float p3 = expf(lrelu(f1i + e3));
            s += p0; s += p1; s += p2; s += p3;
            acc += p0*w0; acc += p1*w1; acc += p2*w2; acc += p3*w3;
        }
        for (; k < cnt; k++){
            int j = jl[k];
            float p = expf(lrelu(f1i + f2B[j*8 + h]));
            s += p;
            acc += p * WhB[(size_t)j*64 + u];
        }
    } else {
        s = (float)N;
        for (int j = 0; j < N; j++) acc += WhB[(size_t)j*64 + u];
    }
    g_hcat[(size_t)row*64 + u] = elu(acc / s);
}

// ---------------- K3: Who = h_cat @ W_out (64 rows/block, float4) ; g1 ; g2 ----------------
__global__ void k3_who(const float* __restrict__ Wout,
                       const float* __restrict__ a1o,
                       const float* __restrict__ a2o){
    __shared__ float Ws[64*32];     // 8 KB
    __shared__ float hs[64*64];     // 16 KB
    __shared__ float a1s[32], a2s[32];
    int t = threadIdx.x;
    for (int i = t; i < 64*32; i += 256) Ws[i] = Wout[i];
    if (t < 32){ a1s[t] = a1o[t]; a2s[t] = a2o[t]; }
    const float4* src = (const float4*)(g_hcat + (size_t)blockIdx.x * 64 * 64);
    float4* hd = (float4*)hs;
    for (int i = t; i < 64*16; i += 256) hd[i] = src[i];
    __syncthreads();

    int w = t >> 5, lane = t & 31;
    float who[8];
#pragma unroll
    for (int r = 0; r < 8; r++) who[r] = 0.f;
    const float4* hrow4 = (const float4*)(hs + (w*8)*64);
#pragma unroll
    for (int f4 = 0; f4 < 16; f4++){
        float w0 = Ws[(4*f4+0)*32 + lane];
        float w1 = Ws[(4*f4+1)*32 + lane];
        float w2 = Ws[(4*f4+2)*32 + lane];
        float w3 = Ws[(4*f4+3)*32 + lane];
#pragma unroll
        for (int r = 0; r < 8; r++){
            float4 hv = hrow4[r*16 + f4];
            who[r] += hv.x*w0 + hv.y*w1 + hv.z*w2 + hv.w*w3;
        }
    }
    int row0 = blockIdx.x*64 + w*8;
    float a1v = a1s[lane], a2v = a2s[lane];
    float v1[8], v2[8];
#pragma unroll
    for (int r = 0; r < 8; r++){
        g_Who[(size_t)(row0+r)*32 + lane] = who[r];
        v1[r] = who[r]*a1v; v2[r] = who[r]*a2v;
    }
#pragma unroll
    for (int o = 16; o; o >>= 1)
#pragma unroll
        for (int r = 0; r < 8; r++){
            v1[r] += __shfl_xor_sync(0xffffffffu, v1[r], o);
            v2[r] += __shfl_xor_sync(0xffffffffu, v2[r], o);
        }
    if (lane == 0)
#pragma unroll
        for (int r = 0; r < 8; r++){ g_g1[row0+r] = v1[r]; g_g2[row0+r] = v2[r]; }
}

// ---------------- K4: layer-2 attention, lane=dim, no max pass, writes outT[k][b] ----------------
__global__ void k4_outattn(){
    int t = threadIdx.x, w = t >> 5, lane = t & 31;
    int row = blockIdx.x * 8 + w;       // = b*512 + i
    int b = row >> 9, i = row & 511;
    int cnt = g_cnt[row];
    const int* __restrict__ jl = g_nbr + (size_t)row * N;

    float g1i = g_g1[row];
    const float* __restrict__ g2b  = g_g2 + b * N;
    const float* __restrict__ WhoB = g_Who + (size_t)b * N * DOUT;

    float s = 0.f, tot = 0.f;
    if (cnt > 0){
        int k = 0;
        for (; k + 4 <= cnt; k += 4){
            int4 j4 = *(const int4*)(jl + k);
            float e0 = g2b[j4.x];
            float e1 = g2b[j4.y];
            float e2 = g2b[j4.z];
            float e3 = g2b[j4.w];
            float w0 = WhoB[(size_t)j4.x*DOUT + lane];
            float w1 = WhoB[(size_t)j4.y*DOUT + lane];
            float w2 = WhoB[(size_t)j4.z*DOUT + lane];
            float w3 = WhoB[(size_t)j4.w*DOUT + lane];
            float p0 = expf(lrelu(g1i + e0));
            float p1 = expf(lrelu(g1i + e1));
            float p2 = expf(lrelu(g1i + e2));
            float p3 = expf(lrelu(g1i + e3));
            s += p0; s += p1; s += p2; s += p3;
            tot += p0*w0; tot += p1*w1; tot += p2*w2; tot += p3*w3;
        }
        for (; k < cnt; k++){
            int j = jl[k];
            float p = expf(lrelu(g1i + g2b[j]));
            s += p;
            tot += p * WhoB[(size_t)j*DOUT + lane];
        }
    } else {
        s = (float)N;
        for (int j = 0; j < N; j++) tot += WhoB[(size_t)j*DOUT + lane];
    }
    // k = i*32 + lane ; outT[k][b]
    g_outT[(size_t)(i*32 + lane)*B + b] = elu(tot / s);
}

// ---------------- K5: register-tiled GEMM  q = out[32,16384] @ Wq[16384,512] ----------------
// grid (8 col-blocks, 32 k-blocks), 256 threads = 4 k-slices x (8 col-groups x 8 b-groups)
// thread tile: 4 b x 8 c ; FFMA2 on col pairs
__global__ void k5_qgemm(const float* __restrict__ Wq){
    __shared__ float outS[64*32];   // [k][b]  8 KB
    __shared__ float wqS[64*64];    // [k][c] 16 KB
    int t = threadIdx.x;
    int slice = t >> 6;             // 0..3
    int u = t & 63;
    int tx = u & 7;                 // col group -> c0 = tx*8
    int ty = u >> 3;                // b group   -> b0 = ty*4
    int b0 = ty*4, c0 = tx*8;
    int cb = blockIdx.x;            // col block (64 cols)
    int ky = blockIdx.y;            // k block (512 k)
    int k0blk = ky * 512;

    ull acc2[16];
#pragma unroll
    for (int q = 0; q < 16; q++) acc2[q] = 0ull;

    for (int st = 0; st < 8; st++){
        int k0 = k0blk + st*64;
        __syncthreads();
        // stage outT rows (coalesced, no transpose)
        {
            const float4* src = (const float4*)(g_outT + (size_t)k0*32);
            float4* dst = (float4*)outS;
            dst[t]       = src[t];
            dst[t + 256] = src[t + 256];
        }
        // stage Wq tile 64k x 64c
#pragma unroll
        for (int i = 0; i < 4; i++){
            int lin = t + i*256;        // 0..1023
            int kk = lin >> 4;
            int cq = lin & 15;
            ((float4*)wqS)[kk*16 + cq] =
                *(const float4*)(Wq + (size_t)(k0 + kk)*512 + cb*64 + cq*4);
        }
        __syncthreads();

        const float* oS = outS + slice*16*32;
        const float* wS = wqS  + slice*16*64;
#pragma unroll
        for (int kk = 0; kk < 16; kk++){
            float4 o4 = *(const float4*)(oS + kk*32 + b0);
            ull ob0 = pack2(o4.x), ob1 = pack2(o4.y), ob2 = pack2(o4.z), ob3 = pack2(o4.w);
            const ull* w2 = (const ull*)(wS + kk*64 + c0);   // 4 ull = 8 cols
#pragma unroll
            for (int cp = 0; cp < 4; cp++){
                ull wv = w2[cp];
                acc2[0*4+cp] = fma2(ob0, wv, acc2[0*4+cp]);
                acc2[1*4+cp] = fma2(ob1, wv, acc2[1*4+cp]);
                acc2[2*4+cp] = fma2(ob2, wv, acc2[2*4+cp]);
                acc2[3*4+cp] = fma2(ob3, wv, acc2[3*4+cp]);
            }
        }
    }
    float* qp = g_qpart + (size_t)(ky*4 + slice) * (B*N);
#pragma unroll
    for (int bb = 0; bb < 4; bb++)
#pragma unroll
        for (int cp = 0; cp < 4; cp++){
            float lo, hi; unpack2(acc2[bb*4+cp], lo, hi);
            int c = cb*64 + c0 + cp*2;
            qp[(b0+bb)*N + c]     = lo;
            qp[(b0+bb)*N + c + 1] = hi;
        }
}

// ---------------- K6: q = sum of 128 partials + b_q ----------------
__global__ void k6_reduce(const float* __restrict__ bq, float* __restrict__ q){
    int t = blockIdx.x * 128 + threadIdx.x;   // [0, 16384)
    int c = t & 511;
    float s = bq[c];
#pragma unroll
    for (int p = 0; p < 128; p++) s += g_qpart[(size_t)p*(B*N) + t];
    q[t] = s;
}

// ---------------- launch ----------------
extern "C" void kernel_launch(void* const* d_in, const int* in_sizes, int n_in,
                              void* d_out, int out_size){
    const float* xv    = (const float*)d_in[0];
    const float* adj   = (const float*)d_in[1];
    const float* Whead = (const float*)d_in[2];
    const float* a1    = (const float*)d_in[3];
    const float* a2    = (const float*)d_in[4];
    const float* Wout  = (const float*)d_in[5];
    const float* a1o   = (const float*)d_in[6];
    const float* a2o   = (const float*)d_in[7];
    const float* Wq    = (const float*)d_in[8];
    const float* bq    = (const float*)d_in[9];
    float* q = (float*)d_out;

    k0_compact<<<B*N/8, 256>>>(adj);
    k1_proj   <<<512, 256>>>(xv, Whead, a1, a2);
    k2_gat    <<<B*N/4, 256>>>();
    k3_who    <<<B*N/64, 256>>>(Wout, a1o, a2o);
    k4_outattn<<<B*N/8, 256>>>();
    k5_qgemm  <<<dim3(8, 32), 256>>>(Wq);
    k6_reduce <<<128, 128>>>(bq, q);
}